// round 1
// baseline (speedup 1.0000x reference)
#include <cuda_runtime.h>
#include <cstddef>

#define BATCH 8
#define NH    16
#define DH    64
#define DIM   1024
#define NFR   16
#define NSP   196
#define NTOK  3137            // 1 + 16*196
#define MTOT  (BATCH*NTOK)    // 25096

// Scratch (device globals: allocation-free per harness rules)
__device__ float g_qkv[(size_t)MTOT * 3 * DIM];   // (b*N, 3072): q|k|v
__device__ float g_attn[(size_t)MTOT * DIM];      // (b*N, 1024) attention output

// ---------------------------------------------------------------------------
// SGEMM: C[m,n] = sum_k A[m,k] * B[n,k] (+ bias[n]); A:MxK row-major,
// B:NxK row-major (i.e. C = A @ B^T). 128x128 block, BK=16, 8x8 per thread.
// ---------------------------------------------------------------------------
__global__ __launch_bounds__(256) void sgemm_nt(
    const float* __restrict__ A, const float* __restrict__ B,
    const float* __restrict__ bias, float* __restrict__ C,
    int M, int N, int K)
{
    const int BK = 16;
    __shared__ float As[BK][128];
    __shared__ float Bs[BK][128];

    const int tid = threadIdx.x;
    const int tx  = tid & 15;
    const int ty  = tid >> 4;
    const int bm  = blockIdx.y * 128;
    const int bn  = blockIdx.x * 128;

    float acc[8][8];
#pragma unroll
    for (int i = 0; i < 8; i++)
#pragma unroll
        for (int j = 0; j < 8; j++) acc[i][j] = 0.0f;

    for (int k0 = 0; k0 < K; k0 += BK) {
        // Each block loads 128x16 of A and of B (512 float4 each; 2/thread each)
#pragma unroll
        for (int i = 0; i < 2; i++) {
            int idx = tid + i * 256;
            int row = idx >> 2;
            int c4  = (idx & 3) << 2;
            int gm  = bm + row;
            float4 va = make_float4(0.f, 0.f, 0.f, 0.f);
            if (gm < M) va = *(const float4*)&A[(size_t)gm * K + k0 + c4];
            As[c4 + 0][row] = va.x; As[c4 + 1][row] = va.y;
            As[c4 + 2][row] = va.z; As[c4 + 3][row] = va.w;
            float4 vb = *(const float4*)&B[(size_t)(bn + row) * K + k0 + c4];
            Bs[c4 + 0][row] = vb.x; Bs[c4 + 1][row] = vb.y;
            Bs[c4 + 2][row] = vb.z; Bs[c4 + 3][row] = vb.w;
        }
        __syncthreads();

#pragma unroll
        for (int k = 0; k < BK; k++) {
            float a[8], b[8];
            *(float4*)&a[0] = *(const float4*)&As[k][ty * 8];
            *(float4*)&a[4] = *(const float4*)&As[k][ty * 8 + 4];
            *(float4*)&b[0] = *(const float4*)&Bs[k][tx * 8];
            *(float4*)&b[4] = *(const float4*)&Bs[k][tx * 8 + 4];
#pragma unroll
            for (int i = 0; i < 8; i++)
#pragma unroll
                for (int j = 0; j < 8; j++)
                    acc[i][j] += a[i] * b[j];
        }
        __syncthreads();
    }

#pragma unroll
    for (int i = 0; i < 8; i++) {
        int gm = bm + ty * 8 + i;
        if (gm >= M) continue;
#pragma unroll
        for (int j = 0; j < 8; j += 4) {
            int gn = bn + tx * 8 + j;
            float4 v;
            v.x = acc[i][j + 0]; v.y = acc[i][j + 1];
            v.z = acc[i][j + 2]; v.w = acc[i][j + 3];
            if (bias) {
                v.x += bias[gn + 0]; v.y += bias[gn + 1];
                v.z += bias[gn + 2]; v.w += bias[gn + 3];
            }
            *(float4*)&C[(size_t)gm * N + gn] = v;
        }
    }
}

// ---------------------------------------------------------------------------
// Spatial attention: one block per (b, h, frame). 197 keys = [cls, frame].
// K/V tile in dynamic smem; one thread per query (q + acc in registers, all
// smem reads are warp-broadcast). Max-free softmax (scores are tiny here).
// ---------------------------------------------------------------------------
#define SPA_THREADS 224
__global__ __launch_bounds__(SPA_THREADS) void spatial_attn(
    const float* __restrict__ qkv, float* __restrict__ out)
{
    extern __shared__ float sm[];
    float* ks = sm;                 // 197*64
    float* vs = sm + 197 * 64;      // 197*64

    const int fb  = blockIdx.x;          // bh*16 + fr
    const int b   = fb >> 8;
    const int h   = (fb >> 4) & 15;
    const int fr  = fb & 15;
    const int tid = threadIdx.x;
    const size_t base = (size_t)b * NTOK * 3 * DIM;

    // Stage K and V for the 197 keys (cls token + 196 frame tokens)
    for (int i = tid; i < 197 * 16; i += SPA_THREADS) {
        int row = i >> 4, c4 = i & 15;
        int gt  = (row == 0) ? 0 : (1 + fr * NSP + row - 1);
        const float4* kp = (const float4*)&qkv[base + (size_t)gt * 3 * DIM + DIM + h * DH];
        ((float4*)ks)[i] = kp[c4];
        ((float4*)vs)[i] = kp[c4 + DIM / 4];   // v is +1024 floats = +256 float4
    }
    __syncthreads();

    if (tid < NSP) {
        const int gq = 1 + fr * NSP + tid;
        const float4* qp = (const float4*)&qkv[base + (size_t)gq * 3 * DIM + h * DH];
        float4 q[16];
#pragma unroll
        for (int d = 0; d < 16; d++) {
            q[d] = qp[d];
            q[d].x *= 0.125f; q[d].y *= 0.125f; q[d].z *= 0.125f; q[d].w *= 0.125f;
        }
        float4 acc[16];
#pragma unroll
        for (int d = 0; d < 16; d++) acc[d] = make_float4(0.f, 0.f, 0.f, 0.f);
        float l = 0.0f;

        for (int t = 0; t < 197; t++) {
            const float4* kr = (const float4*)&ks[t * 64];
            float s = 0.0f;
#pragma unroll
            for (int d = 0; d < 16; d++) {
                float4 kk = kr[d];
                s += q[d].x * kk.x + q[d].y * kk.y + q[d].z * kk.z + q[d].w * kk.w;
            }
            float p = __expf(s);
            l += p;
            const float4* vr = (const float4*)&vs[t * 64];
#pragma unroll
            for (int d = 0; d < 16; d++) {
                float4 vv = vr[d];
                acc[d].x += p * vv.x; acc[d].y += p * vv.y;
                acc[d].z += p * vv.z; acc[d].w += p * vv.w;
            }
        }
        float inv = 1.0f / l;
        float4* op = (float4*)&out[((size_t)(b * NTOK + gq)) * DIM + h * DH];
#pragma unroll
        for (int d = 0; d < 16; d++) {
            float4 o;
            o.x = acc[d].x * inv; o.y = acc[d].y * inv;
            o.z = acc[d].z * inv; o.w = acc[d].w * inv;
            op[d] = o;
        }
    }
}

// ---------------------------------------------------------------------------
// CLS attention: one block per (b, h); the single cls query attends over all
// 3137 keys. 8 warps stride the keys; cross-warp merge via smem.
// ---------------------------------------------------------------------------
__global__ __launch_bounds__(256) void cls_attn(
    const float* __restrict__ qkv, float* __restrict__ out)
{
    const int bh   = blockIdx.x;
    const int b    = bh >> 4, h = bh & 15;
    const int warp = threadIdx.x >> 5, lane = threadIdx.x & 31;
    __shared__ float s_l[8];
    __shared__ float s_acc[8][64];

    const size_t base = (size_t)b * NTOK * 3 * DIM;
    const float* qp = &qkv[base + h * DH];        // cls token q
    const float q0 = qp[lane] * 0.125f;
    const float q1 = qp[lane + 32] * 0.125f;

    float l = 0.f, a0 = 0.f, a1 = 0.f;
    for (int t = warp; t < NTOK; t += 8) {
        const float* kp = &qkv[base + (size_t)t * 3 * DIM + DIM + h * DH];
        float s = q0 * kp[lane] + q1 * kp[lane + 32];
#pragma unroll
        for (int off = 16; off > 0; off >>= 1)
            s += __shfl_xor_sync(0xffffffffu, s, off);
        float p = __expf(s);
        const float* vp = kp + DIM;
        l  += p;
        a0 += p * vp[lane];
        a1 += p * vp[lane + 32];
    }
    s_acc[warp][lane]      = a0;
    s_acc[warp][lane + 32] = a1;
    if (lane == 0) s_l[warp] = l;
    __syncthreads();

    if (warp == 0) {
        float L = 0.f, o0 = 0.f, o1 = 0.f;
#pragma unroll
        for (int w = 0; w < 8; w++) {
            L  += s_l[w];
            o0 += s_acc[w][lane];
            o1 += s_acc[w][lane + 32];
        }
        float inv = 1.0f / L;
        float* op = &out[(size_t)b * NTOK * DIM + h * DH];
        op[lane]      = o0 * inv;
        op[lane + 32] = o1 * inv;
    }
}

// ---------------------------------------------------------------------------
extern "C" void kernel_launch(void* const* d_in, const int* in_sizes, int n_in,
                              void* d_out, int out_size)
{
    const float* x      = (const float*)d_in[0];
    const float* qkv_w  = (const float*)d_in[1];
    const float* proj_w = (const float*)d_in[2];
    const float* proj_b = (const float*)d_in[3];
    float* out = (float*)d_out;

    float *qkv, *attn;
    cudaGetSymbolAddress((void**)&qkv, g_qkv);
    cudaGetSymbolAddress((void**)&attn, g_attn);

    const int SPA_SMEM = 2 * 197 * 64 * (int)sizeof(float);   // 100864 B
    cudaFuncSetAttribute(spatial_attn,
                         cudaFuncAttributeMaxDynamicSharedMemorySize, SPA_SMEM);

    // 1) qkv = x @ qkv_w^T  : (25096 x 3072)
    dim3 g1(3 * DIM / 128, (MTOT + 127) / 128);
    sgemm_nt<<<g1, 256>>>(x, qkv_w, nullptr, qkv, MTOT, 3 * DIM, DIM);

    // 2) attention
    spatial_attn<<<BATCH * NH * NFR, SPA_THREADS, SPA_SMEM>>>(qkv, attn);
    cls_attn<<<BATCH * NH, 256>>>(qkv, attn);

    // 3) out = attn @ proj_w^T + proj_b : (25096 x 1024)
    dim3 g2(DIM / 128, (MTOT + 127) / 128);
    sgemm_nt<<<g2, 256>>>(attn, proj_w, proj_b, out, MTOT, DIM, DIM);
}

// round 4
// speedup vs baseline: 1.9975x; 1.9975x over previous
#include <cuda_runtime.h>
#include <cuda_bf16.h>
#include <cstdint>
#include <cstddef>

#define BATCH 8
#define NH    16
#define DH    64
#define DIM   1024
#define NFR   16
#define NSP   196
#define NTOK  3137            // 1 + 16*196
#define MTOT  (BATCH*NTOK)    // 25096
#define MPAD  (197*128)       // 25216 (padded to M-tile multiple)

// ---------------- scratch (device globals; allocation-free) ----------------
__device__ float g_qkv[(size_t)MTOT * 3 * DIM];     // fp32 qkv for attention
__device__ __nv_bfloat16 g_xhi[(size_t)MPAD * DIM];
__device__ __nv_bfloat16 g_xlo[(size_t)MPAD * DIM];
__device__ __nv_bfloat16 g_ahi[(size_t)MPAD * DIM];
__device__ __nv_bfloat16 g_alo[(size_t)MPAD * DIM];
__device__ __nv_bfloat16 g_w1hi[(size_t)3 * DIM * DIM];
__device__ __nv_bfloat16 g_w1lo[(size_t)3 * DIM * DIM];
__device__ __nv_bfloat16 g_w2hi[(size_t)DIM * DIM];
__device__ __nv_bfloat16 g_w2lo[(size_t)DIM * DIM];

// ---------------- PTX helpers ----------------
__device__ __forceinline__ uint32_t smem_u32(const void* p) {
    uint32_t a;
    asm("{ .reg .u64 t; cvta.to.shared.u64 t, %1; cvt.u32.u64 %0, t; }" : "=r"(a) : "l"(p));
    return a;
}
__device__ __forceinline__ void cpa16(uint32_t s, const void* g) {
    asm volatile("cp.async.ca.shared.global [%0], [%1], 16;" :: "r"(s), "l"(g) : "memory");
}
__device__ __forceinline__ void cpa_commit() { asm volatile("cp.async.commit_group;" ::: "memory"); }
__device__ __forceinline__ void cpa_wait1()  { asm volatile("cp.async.wait_group 1;" ::: "memory"); }

__device__ __forceinline__ void ldm4(uint32_t* r, uint32_t a) {
    asm volatile("ldmatrix.sync.aligned.m8n8.x4.shared.b16 {%0,%1,%2,%3}, [%4];"
        : "=r"(r[0]), "=r"(r[1]), "=r"(r[2]), "=r"(r[3]) : "r"(a));
}
__device__ __forceinline__ void mma16816(float* d, const uint32_t* a, const uint32_t* b) {
    asm volatile("mma.sync.aligned.m16n8k16.row.col.f32.bf16.bf16.f32 "
        "{%0,%1,%2,%3}, {%4,%5,%6,%7}, {%8,%9}, {%0,%1,%2,%3};"
        : "+f"(d[0]), "+f"(d[1]), "+f"(d[2]), "+f"(d[3])
        : "r"(a[0]), "r"(a[1]), "r"(a[2]), "r"(a[3]), "r"(b[0]), "r"(b[1]));
}

// packed f32x2 helpers
typedef unsigned long long u64t;
__device__ __forceinline__ u64t ffma2(u64t a, u64t b, u64t c) {
    u64t d; asm("fma.rn.f32x2 %0, %1, %2, %3;" : "=l"(d) : "l"(a), "l"(b), "l"(c)); return d;
}
__device__ __forceinline__ u64t fmul2(u64t a, u64t b) {
    u64t d; asm("mul.rn.f32x2 %0, %1, %2;" : "=l"(d) : "l"(a), "l"(b)); return d;
}
__device__ __forceinline__ u64t fpack2(float lo, float hi) {
    u64t d; asm("mov.b64 %0, {%1, %2};" : "=l"(d) : "f"(lo), "f"(hi)); return d;
}
__device__ __forceinline__ void funpack2(u64t v, float& lo, float& hi) {
    asm("mov.b64 {%0, %1}, %2;" : "=f"(lo), "=f"(hi) : "l"(v));
}

// ---------------------------------------------------------------------------
// fp32 -> bf16 hi/lo split
// ---------------------------------------------------------------------------
__global__ __launch_bounds__(256) void cvt_split(
    const float* __restrict__ in, __nv_bfloat16* __restrict__ hi,
    __nv_bfloat16* __restrict__ lo, int n4)
{
    int i = blockIdx.x * blockDim.x + threadIdx.x;
    if (i >= n4) return;
    float4 v = ((const float4*)in)[i];
    __nv_bfloat16 h0 = __float2bfloat16(v.x), h1 = __float2bfloat16(v.y);
    __nv_bfloat16 h2 = __float2bfloat16(v.z), h3 = __float2bfloat16(v.w);
    __nv_bfloat16 l0 = __float2bfloat16(v.x - __bfloat162float(h0));
    __nv_bfloat16 l1 = __float2bfloat16(v.y - __bfloat162float(h1));
    __nv_bfloat16 l2 = __float2bfloat16(v.z - __bfloat162float(h2));
    __nv_bfloat16 l3 = __float2bfloat16(v.w - __bfloat162float(h3));
    ((__nv_bfloat162*)hi)[2*i]   = __nv_bfloat162(h0, h1);
    ((__nv_bfloat162*)hi)[2*i+1] = __nv_bfloat162(h2, h3);
    ((__nv_bfloat162*)lo)[2*i]   = __nv_bfloat162(l0, l1);
    ((__nv_bfloat162*)lo)[2*i+1] = __nv_bfloat162(l2, l3);
}

// ---------------------------------------------------------------------------
// HMMA bf16x3 GEMM: C[m,n] = sum_k A[m,k]*B[n,k] (+bias), fp32-equivalent via
// hi/lo bf16 split (AhBh + AhBl + AlBh). 128x128x32 CTA tile, 3-stage
// cp.async pipeline, 8 warps (4m x 2n), warp tile 32x64, mma.m16n8k16.
// K is fixed at 1024 for both GEMMs.
// ---------------------------------------------------------------------------
#define STG_B  32768
#define AH_OFF 0
#define AL_OFF 8192
#define BH_OFF 16384
#define BL_OFF 24576
#define GSMEM  (3 * STG_B)     // 98304
#define KITERS 32              // 1024 / 32

__device__ __forceinline__ void ld_stage(
    uint32_t dst, const char* a0, const char* a1, const char* b0, const char* b1,
    int k0, int tid)
{
    size_t kb = (size_t)k0 * 2;
#pragma unroll
    for (int i = 0; i < 2; ++i) {
        int idx = tid + (i << 8);              // 0..511
        uint32_t r = idx >> 2, c = idx & 3;    // row, 16B-chunk
        uint32_t phys = r * 64 + ((c ^ ((r >> 1) & 3)) << 4);
        size_t go = (size_t)r * 2048 + kb + c * 16;
        cpa16(dst + AH_OFF + phys, a0 + go);
        cpa16(dst + AL_OFF + phys, a1 + go);
        cpa16(dst + BH_OFF + phys, b0 + go);
        cpa16(dst + BL_OFF + phys, b1 + go);
    }
}

__global__ __launch_bounds__(256, 1) void gemm_bf16x3(
    const __nv_bfloat16* __restrict__ Ahi, const __nv_bfloat16* __restrict__ Alo,
    const __nv_bfloat16* __restrict__ Bhi, const __nv_bfloat16* __restrict__ Blo,
    const float* __restrict__ bias, float* __restrict__ C, int M, int N)
{
    extern __shared__ char smem[];
    const uint32_t sb = smem_u32(smem);
    const int tid = threadIdx.x, lane = tid & 31, wid = tid >> 5;
    const int wm = (wid & 3) * 32;    // warp row offset in block
    const int wn = (wid >> 2) * 64;   // warp col offset
    const int bm = blockIdx.y * 128, bn = blockIdx.x * 128;

    const char* a0 = (const char*)(Ahi + (size_t)bm * 1024);
    const char* a1 = (const char*)(Alo + (size_t)bm * 1024);
    const char* b0 = (const char*)(Bhi + (size_t)bn * 1024);
    const char* b1 = (const char*)(Blo + (size_t)bn * 1024);

    float acc[2][8][4];
#pragma unroll
    for (int i = 0; i < 2; i++)
#pragma unroll
        for (int j = 0; j < 8; j++)
#pragma unroll
            for (int q = 0; q < 4; q++) acc[i][j][q] = 0.f;

    ld_stage(sb,         a0, a1, b0, b1, 0,  tid); cpa_commit();
    ld_stage(sb + STG_B, a0, a1, b0, b1, 32, tid); cpa_commit();

#pragma unroll 1
    for (int it = 0; it < KITERS; ++it) {
        cpa_wait1();
        __syncthreads();
        if (it + 2 < KITERS)
            ld_stage(sb + ((it + 2) % 3) * STG_B, a0, a1, b0, b1, (it + 2) * 32, tid);
        cpa_commit();

        const uint32_t stg = sb + (it % 3) * STG_B;
#pragma unroll
        for (int ks = 0; ks < 2; ++ks) {
            uint32_t ah[2][4], al_[2][4];
#pragma unroll
            for (int mt = 0; mt < 2; ++mt) {
                uint32_t row = wm + mt * 16 + (lane & 15);
                uint32_t c = ks * 2 + (lane >> 4);
                uint32_t phys = row * 64 + ((c ^ ((row >> 1) & 3)) << 4);
                ldm4(ah[mt],  stg + AH_OFF + phys);
                ldm4(al_[mt], stg + AL_OFF + phys);
            }
            uint32_t bh[4][4], bl_[4][4];
#pragma unroll
            for (int nq = 0; nq < 4; ++nq) {
                uint32_t row = wn + nq * 16 + ((lane >> 4) << 3) + (lane & 7);
                uint32_t c = ks * 2 + ((lane >> 3) & 1);
                uint32_t phys = row * 64 + ((c ^ ((row >> 1) & 3)) << 4);
                ldm4(bh[nq],  stg + BH_OFF + phys);
                ldm4(bl_[nq], stg + BL_OFF + phys);
            }
#pragma unroll
            for (int mt = 0; mt < 2; ++mt)
#pragma unroll
                for (int nq = 0; nq < 4; ++nq)
#pragma unroll
                    for (int h2 = 0; h2 < 2; ++h2) {
                        float* d = acc[mt][nq * 2 + h2];
                        mma16816(d, ah[mt],  &bh[nq][h2 * 2]);
                        mma16816(d, ah[mt],  &bl_[nq][h2 * 2]);
                        mma16816(d, al_[mt], &bh[nq][h2 * 2]);
                    }
        }
    }

    // epilogue
#pragma unroll
    for (int mt = 0; mt < 2; ++mt) {
        int r0g = bm + wm + mt * 16 + (lane >> 2);
#pragma unroll
        for (int half = 0; half < 2; ++half) {
            int rg = r0g + half * 8;
            if (rg < M) {
                int cbase = bn + wn + (lane & 3) * 2;
                float* crow = &C[(size_t)rg * N + cbase];
#pragma unroll
                for (int nt = 0; nt < 8; ++nt) {
                    float2 v;
                    v.x = acc[mt][nt][half * 2 + 0];
                    v.y = acc[mt][nt][half * 2 + 1];
                    if (bias) {
                        v.x += bias[cbase + nt * 8];
                        v.y += bias[cbase + nt * 8 + 1];
                    }
                    *(float2*)(crow + nt * 8) = v;
                }
            }
        }
    }
}

// ---------------------------------------------------------------------------
// Spatial attention (packed f32x2). One block per (b, h, frame).
// Writes bf16 hi/lo split directly (feeds GEMM2).
// ---------------------------------------------------------------------------
#define SPA_THREADS 224
__global__ __launch_bounds__(SPA_THREADS) void spatial_attn(
    const float* __restrict__ qkv,
    __nv_bfloat16* __restrict__ ohi, __nv_bfloat16* __restrict__ olo)
{
    extern __shared__ float sm[];
    float* ks = sm;                 // 197*64
    float* vs = sm + 197 * 64;

    const int fb  = blockIdx.x;
    const int b   = fb >> 8;
    const int h   = (fb >> 4) & 15;
    const int fr  = fb & 15;
    const int tid = threadIdx.x;
    const size_t base = (size_t)b * NTOK * 3 * DIM;

    for (int i = tid; i < 197 * 16; i += SPA_THREADS) {
        int row = i >> 4, c4 = i & 15;
        int gt  = (row == 0) ? 0 : (1 + fr * NSP + row - 1);
        const float4* kp = (const float4*)&qkv[base + (size_t)gt * 3 * DIM + DIM + h * DH];
        ((float4*)ks)[i] = kp[c4];
        ((float4*)vs)[i] = kp[c4 + DIM / 4];
    }
    __syncthreads();

    if (tid < NSP) {
        const int gq = 1 + fr * NSP + tid;
        const u64t* qp = (const u64t*)&qkv[base + (size_t)gq * 3 * DIM + h * DH];
        const u64t sc = fpack2(0.125f, 0.125f);
        u64t q2[32];
#pragma unroll
        for (int i = 0; i < 32; i++) q2[i] = fmul2(qp[i], sc);
        u64t acc2[32];
#pragma unroll
        for (int i = 0; i < 32; i++) acc2[i] = 0ull;
        float l = 0.0f;

        const u64t* ks2 = (const u64t*)ks;
        const u64t* vs2 = (const u64t*)vs;
#pragma unroll 1
        for (int t = 0; t < 197; t++) {
            const u64t* kr = ks2 + t * 32;
            u64t sp = 0ull;
#pragma unroll
            for (int i = 0; i < 32; i++) sp = ffma2(q2[i], kr[i], sp);
            float slo, shi; funpack2(sp, slo, shi);
            float p = __expf(slo + shi);
            l += p;
            u64t pp = fpack2(p, p);
            const u64t* vr = vs2 + t * 32;
#pragma unroll
            for (int i = 0; i < 32; i++) acc2[i] = ffma2(pp, vr[i], acc2[i]);
        }
        u64t inv2 = fpack2(1.0f / l, 1.0f / l);
        size_t o = ((size_t)(b * NTOK + gq)) * DIM + h * DH;
        __nv_bfloat162* hp = (__nv_bfloat162*)&ohi[o];
        __nv_bfloat162* lp = (__nv_bfloat162*)&olo[o];
#pragma unroll
        for (int i = 0; i < 32; i++) {
            float e0, e1; funpack2(fmul2(acc2[i], inv2), e0, e1);
            __nv_bfloat16 h0 = __float2bfloat16(e0);
            __nv_bfloat16 h1 = __float2bfloat16(e1);
            __nv_bfloat16 l0 = __float2bfloat16(e0 - __bfloat162float(h0));
            __nv_bfloat16 l1 = __float2bfloat16(e1 - __bfloat162float(h1));
            hp[i] = __nv_bfloat162(h0, h1);
            lp[i] = __nv_bfloat162(l0, l1);
        }
    }
}

// ---------------------------------------------------------------------------
// CLS attention: one block per (b, h); writes hi/lo split.
// ---------------------------------------------------------------------------
__global__ __launch_bounds__(256) void cls_attn(
    const float* __restrict__ qkv,
    __nv_bfloat16* __restrict__ ohi, __nv_bfloat16* __restrict__ olo)
{
    const int bh   = blockIdx.x;
    const int b    = bh >> 4, h = bh & 15;
    const int warp = threadIdx.x >> 5, lane = threadIdx.x & 31;
    __shared__ float s_l[8];
    __shared__ float s_acc[8][64];

    const size_t base = (size_t)b * NTOK * 3 * DIM;
    const float* qp = &qkv[base + h * DH];
    const float q0 = qp[lane] * 0.125f;
    const float q1 = qp[lane + 32] * 0.125f;

    float l = 0.f, a0 = 0.f, a1 = 0.f;
    for (int t = warp; t < NTOK; t += 8) {
        const float* kp = &qkv[base + (size_t)t * 3 * DIM + DIM + h * DH];
        float s = q0 * kp[lane] + q1 * kp[lane + 32];
#pragma unroll
        for (int off = 16; off > 0; off >>= 1)
            s += __shfl_xor_sync(0xffffffffu, s, off);
        float p = __expf(s);
        const float* vp = kp + DIM;
        l  += p;
        a0 += p * vp[lane];
        a1 += p * vp[lane + 32];
    }
    s_acc[warp][lane]      = a0;
    s_acc[warp][lane + 32] = a1;
    if (lane == 0) s_l[warp] = l;
    __syncthreads();

    if (warp == 0) {
        float L = 0.f, o0 = 0.f, o1 = 0.f;
#pragma unroll
        for (int w = 0; w < 8; w++) {
            L  += s_l[w];
            o0 += s_acc[w][lane];
            o1 += s_acc[w][lane + 32];
        }
        float inv = 1.0f / L;
        size_t o = (size_t)b * NTOK * DIM + h * DH;
        float v0 = o0 * inv, v1 = o1 * inv;
        __nv_bfloat16 h0 = __float2bfloat16(v0);
        __nv_bfloat16 h1 = __float2bfloat16(v1);
        ohi[o + lane]      = h0;
        ohi[o + lane + 32] = h1;
        olo[o + lane]      = __float2bfloat16(v0 - __bfloat162float(h0));
        olo[o + lane + 32] = __float2bfloat16(v1 - __bfloat162float(h1));
    }
}

// ---------------------------------------------------------------------------
extern "C" void kernel_launch(void* const* d_in, const int* in_sizes, int n_in,
                              void* d_out, int out_size)
{
    const float* x      = (const float*)d_in[0];
    const float* qkv_w  = (const float*)d_in[1];
    const float* proj_w = (const float*)d_in[2];
    const float* proj_b = (const float*)d_in[3];
    float* out = (float*)d_out;

    float *qkv;
    __nv_bfloat16 *xhi, *xlo, *ahi, *alo, *w1hi, *w1lo, *w2hi, *w2lo;
    cudaGetSymbolAddress((void**)&qkv,  g_qkv);
    cudaGetSymbolAddress((void**)&xhi,  g_xhi);
    cudaGetSymbolAddress((void**)&xlo,  g_xlo);
    cudaGetSymbolAddress((void**)&ahi,  g_ahi);
    cudaGetSymbolAddress((void**)&alo,  g_alo);
    cudaGetSymbolAddress((void**)&w1hi, g_w1hi);
    cudaGetSymbolAddress((void**)&w1lo, g_w1lo);
    cudaGetSymbolAddress((void**)&w2hi, g_w2hi);
    cudaGetSymbolAddress((void**)&w2lo, g_w2lo);

    const int SPA_SMEM = 2 * 197 * 64 * (int)sizeof(float);
    cudaFuncSetAttribute(spatial_attn, cudaFuncAttributeMaxDynamicSharedMemorySize, SPA_SMEM);
    cudaFuncSetAttribute(gemm_bf16x3,  cudaFuncAttributeMaxDynamicSharedMemorySize, GSMEM);

    // conversions
    {
        int n4 = MTOT * DIM / 4;
        cvt_split<<<(n4 + 255) / 256, 256>>>(x, xhi, xlo, n4);
        n4 = 3 * DIM * DIM / 4;
        cvt_split<<<(n4 + 255) / 256, 256>>>(qkv_w, w1hi, w1lo, n4);
        n4 = DIM * DIM / 4;
        cvt_split<<<(n4 + 255) / 256, 256>>>(proj_w, w2hi, w2lo, n4);
    }

    // 1) qkv = x @ qkv_w^T : (25096 x 3072)
    gemm_bf16x3<<<dim3(3 * DIM / 128, 197), 256, GSMEM>>>(
        xhi, xlo, w1hi, w1lo, nullptr, qkv, MTOT, 3 * DIM);

    // 2) attention (writes bf16 hi/lo split directly)
    spatial_attn<<<BATCH * NH * NFR, SPA_THREADS, SPA_SMEM>>>(qkv, ahi, alo);
    cls_attn<<<BATCH * NH, 256>>>(qkv, ahi, alo);

    // 3) out = attn @ proj_w^T + proj_b : (25096 x 1024)
    gemm_bf16x3<<<dim3(DIM / 128, 197), 256, GSMEM>>>(
        ahi, alo, w2hi, w2lo, proj_b, out, MTOT, DIM);
}

// round 5
// speedup vs baseline: 3.5712x; 1.7879x over previous
#include <cuda_runtime.h>
#include <cuda_fp16.h>
#include <cstdint>
#include <cstddef>

#define BATCH 8
#define NH    16
#define DH    64
#define DIM   1024
#define NFR   16
#define NSP   196
#define NTOK  3137            // 1 + 16*196
#define MTOT  (BATCH*NTOK)    // 25096
#define MPAD  (197*128)       // 25216

// ---------------- scratch (device globals; allocation-free) ----------------
__device__ float  g_qkv[(size_t)MTOT * 3 * DIM];   // fp32 qkv for attention
__device__ __half g_xh[(size_t)MPAD * DIM];        // x in fp16
__device__ __half g_ah[(size_t)MPAD * DIM];        // attention out in fp16
__device__ __half g_w1h[(size_t)3 * DIM * DIM];
__device__ __half g_w2h[(size_t)DIM * DIM];

// ---------------- PTX helpers ----------------
__device__ __forceinline__ uint32_t smem_u32(const void* p) {
    uint32_t a;
    asm("{ .reg .u64 t; cvta.to.shared.u64 t, %1; cvt.u32.u64 %0, t; }" : "=r"(a) : "l"(p));
    return a;
}
__device__ __forceinline__ void cpa16(uint32_t s, const void* g) {
    asm volatile("cp.async.ca.shared.global [%0], [%1], 16;" :: "r"(s), "l"(g) : "memory");
}
__device__ __forceinline__ void cpa_commit() { asm volatile("cp.async.commit_group;" ::: "memory"); }
__device__ __forceinline__ void cpa_wait1()  { asm volatile("cp.async.wait_group 1;" ::: "memory"); }

__device__ __forceinline__ void ldm4(uint32_t* r, uint32_t a) {
    asm volatile("ldmatrix.sync.aligned.m8n8.x4.shared.b16 {%0,%1,%2,%3}, [%4];"
        : "=r"(r[0]), "=r"(r[1]), "=r"(r[2]), "=r"(r[3]) : "r"(a));
}
__device__ __forceinline__ void mma16816(float* d, const uint32_t* a, const uint32_t* b) {
    asm volatile("mma.sync.aligned.m16n8k16.row.col.f32.f16.f16.f32 "
        "{%0,%1,%2,%3}, {%4,%5,%6,%7}, {%8,%9}, {%0,%1,%2,%3};"
        : "+f"(d[0]), "+f"(d[1]), "+f"(d[2]), "+f"(d[3])
        : "r"(a[0]), "r"(a[1]), "r"(a[2]), "r"(a[3]), "r"(b[0]), "r"(b[1]));
}

// packed f32x2 helpers
typedef unsigned long long u64t;
__device__ __forceinline__ u64t ffma2(u64t a, u64t b, u64t c) {
    u64t d; asm("fma.rn.f32x2 %0, %1, %2, %3;" : "=l"(d) : "l"(a), "l"(b), "l"(c)); return d;
}
__device__ __forceinline__ u64t fmul2(u64t a, u64t b) {
    u64t d; asm("mul.rn.f32x2 %0, %1, %2;" : "=l"(d) : "l"(a), "l"(b)); return d;
}
__device__ __forceinline__ u64t fpack2(float lo, float hi) {
    u64t d; asm("mov.b64 %0, {%1, %2};" : "=l"(d) : "f"(lo), "f"(hi)); return d;
}
__device__ __forceinline__ void funpack2(u64t v, float& lo, float& hi) {
    asm("mov.b64 {%0, %1}, %2;" : "=f"(lo), "=f"(hi) : "l"(v));
}

// ---------------------------------------------------------------------------
// fp32 -> fp16 convert (vectorized)
// ---------------------------------------------------------------------------
__global__ __launch_bounds__(256) void cvt_h(
    const float* __restrict__ in, __half* __restrict__ out, int n4)
{
    int i = blockIdx.x * blockDim.x + threadIdx.x;
    if (i >= n4) return;
    float4 v = ((const float4*)in)[i];
    ((__half2*)out)[2*i]   = __floats2half2_rn(v.x, v.y);
    ((__half2*)out)[2*i+1] = __floats2half2_rn(v.z, v.w);
}

// ---------------------------------------------------------------------------
// HMMA fp16 GEMM: C[m,n] = sum_k A[m,k]*B[n,k] (+bias). 128x128x64 CTA tile,
// 3-stage cp.async pipeline (32KB/stage), 8 warps (4m x 2n), warp tile 32x64.
// K fixed at 1024. 2 CTAs/SM.
// ---------------------------------------------------------------------------
#define STG_B  32768            // 16KB A + 16KB B
#define B_OFF  16384
#define GSMEM  (3 * STG_B)      // 98304
#define KITERS 16               // 1024 / 64

__device__ __forceinline__ void ld_stage(
    uint32_t dst, const char* A, const char* B, int k0, int tid)
{
    size_t kb = (size_t)k0 * 2;
#pragma unroll
    for (int i = 0; i < 4; ++i) {
        int idx = tid + (i << 8);              // 0..1023
        uint32_t r = idx >> 3, c = idx & 7;    // row 0..127, 16B-chunk 0..7
        uint32_t phys = r * 128 + ((c ^ (r & 7)) << 4);
        size_t go = (size_t)r * 2048 + kb + c * 16;
        cpa16(dst + phys,         A + go);
        cpa16(dst + B_OFF + phys, B + go);
    }
}

__global__ __launch_bounds__(256, 2) void gemm_h(
    const __half* __restrict__ Ah, const __half* __restrict__ Bh,
    const float* __restrict__ bias, float* __restrict__ C, int M, int N)
{
    extern __shared__ char smem[];
    const uint32_t sb = smem_u32(smem);
    const int tid = threadIdx.x, lane = tid & 31, wid = tid >> 5;
    const int wm = (wid & 3) * 32;
    const int wn = (wid >> 2) * 64;
    const int bm = blockIdx.y * 128, bn = blockIdx.x * 128;

    const char* a0 = (const char*)(Ah + (size_t)bm * 1024);
    const char* b0 = (const char*)(Bh + (size_t)bn * 1024);

    float acc[2][8][4];
#pragma unroll
    for (int i = 0; i < 2; i++)
#pragma unroll
        for (int j = 0; j < 8; j++)
#pragma unroll
            for (int q = 0; q < 4; q++) acc[i][j][q] = 0.f;

    ld_stage(sb,         a0, b0, 0,  tid); cpa_commit();
    ld_stage(sb + STG_B, a0, b0, 64, tid); cpa_commit();

#pragma unroll 1
    for (int it = 0; it < KITERS; ++it) {
        cpa_wait1();
        __syncthreads();
        if (it + 2 < KITERS)
            ld_stage(sb + ((it + 2) % 3) * STG_B, a0, b0, (it + 2) * 64, tid);
        cpa_commit();

        const uint32_t stg = sb + (it % 3) * STG_B;
#pragma unroll
        for (int ks = 0; ks < 4; ++ks) {
            uint32_t ah[2][4];
#pragma unroll
            for (int mt = 0; mt < 2; ++mt) {
                uint32_t row = wm + mt * 16 + (lane & 15);
                uint32_t c = ks * 2 + (lane >> 4);
                uint32_t phys = row * 128 + ((c ^ (row & 7)) << 4);
                ldm4(ah[mt], stg + phys);
            }
            uint32_t bh[4][4];
#pragma unroll
            for (int nq = 0; nq < 4; ++nq) {
                uint32_t row = wn + nq * 16 + ((lane >> 4) << 3) + (lane & 7);
                uint32_t c = ks * 2 + ((lane >> 3) & 1);
                uint32_t phys = row * 128 + ((c ^ (row & 7)) << 4);
                ldm4(bh[nq], stg + B_OFF + phys);
            }
#pragma unroll
            for (int mt = 0; mt < 2; ++mt)
#pragma unroll
                for (int nq = 0; nq < 4; ++nq)
#pragma unroll
                    for (int h2 = 0; h2 < 2; ++h2)
                        mma16816(acc[mt][nq * 2 + h2], ah[mt], &bh[nq][h2 * 2]);
        }
    }

    // epilogue
#pragma unroll
    for (int mt = 0; mt < 2; ++mt) {
        int r0g = bm + wm + mt * 16 + (lane >> 2);
#pragma unroll
        for (int half = 0; half < 2; ++half) {
            int rg = r0g + half * 8;
            if (rg < M) {
                int cbase = bn + wn + (lane & 3) * 2;
                float* crow = &C[(size_t)rg * N + cbase];
#pragma unroll
                for (int nt = 0; nt < 8; ++nt) {
                    float2 v;
                    v.x = acc[mt][nt][half * 2 + 0];
                    v.y = acc[mt][nt][half * 2 + 1];
                    if (bias) {
                        v.x += bias[cbase + nt * 8];
                        v.y += bias[cbase + nt * 8 + 1];
                    }
                    *(float2*)(crow + nt * 8) = v;
                }
            }
        }
    }
}

// ---------------------------------------------------------------------------
// Spatial attention (packed f32x2). One block per (b, h, frame).
// Writes fp16 directly (feeds GEMM2).
// ---------------------------------------------------------------------------
#define SPA_THREADS 224
__global__ __launch_bounds__(SPA_THREADS) void spatial_attn(
    const float* __restrict__ qkv, __half* __restrict__ oh)
{
    extern __shared__ float sm[];
    float* ks = sm;                 // 197*64
    float* vs = sm + 197 * 64;

    const int fb  = blockIdx.x;
    const int b   = fb >> 8;
    const int h   = (fb >> 4) & 15;
    const int fr  = fb & 15;
    const int tid = threadIdx.x;
    const size_t base = (size_t)b * NTOK * 3 * DIM;

    for (int i = tid; i < 197 * 16; i += SPA_THREADS) {
        int row = i >> 4, c4 = i & 15;
        int gt  = (row == 0) ? 0 : (1 + fr * NSP + row - 1);
        const float4* kp = (const float4*)&qkv[base + (size_t)gt * 3 * DIM + DIM + h * DH];
        ((float4*)ks)[i] = kp[c4];
        ((float4*)vs)[i] = kp[c4 + DIM / 4];
    }
    __syncthreads();

    if (tid < NSP) {
        const int gq = 1 + fr * NSP + tid;
        const u64t* qp = (const u64t*)&qkv[base + (size_t)gq * 3 * DIM + h * DH];
        const u64t sc = fpack2(0.125f, 0.125f);
        u64t q2[32];
#pragma unroll
        for (int i = 0; i < 32; i++) q2[i] = fmul2(qp[i], sc);
        u64t acc2[32];
#pragma unroll
        for (int i = 0; i < 32; i++) acc2[i] = 0ull;
        float l = 0.0f;

        const u64t* ks2 = (const u64t*)ks;
        const u64t* vs2 = (const u64t*)vs;
#pragma unroll 1
        for (int t = 0; t < 197; t++) {
            const u64t* kr = ks2 + t * 32;
            u64t sp = 0ull;
#pragma unroll
            for (int i = 0; i < 32; i++) sp = ffma2(q2[i], kr[i], sp);
            float slo, shi; funpack2(sp, slo, shi);
            float p = __expf(slo + shi);
            l += p;
            u64t pp = fpack2(p, p);
            const u64t* vr = vs2 + t * 32;
#pragma unroll
            for (int i = 0; i < 32; i++) acc2[i] = ffma2(pp, vr[i], acc2[i]);
        }
        u64t inv2 = fpack2(1.0f / l, 1.0f / l);
        __half2* hp = (__half2*)&oh[((size_t)(b * NTOK + gq)) * DIM + h * DH];
#pragma unroll
        for (int i = 0; i < 32; i++) {
            float e0, e1; funpack2(fmul2(acc2[i], inv2), e0, e1);
            hp[i] = __floats2half2_rn(e0, e1);
        }
    }
}

// ---------------------------------------------------------------------------
// CLS attention: one block per (b, h); writes fp16.
// ---------------------------------------------------------------------------
__global__ __launch_bounds__(256) void cls_attn(
    const float* __restrict__ qkv, __half* __restrict__ oh)
{
    const int bh   = blockIdx.x;
    const int b    = bh >> 4, h = bh & 15;
    const int warp = threadIdx.x >> 5, lane = threadIdx.x & 31;
    __shared__ float s_l[8];
    __shared__ float s_acc[8][64];

    const size_t base = (size_t)b * NTOK * 3 * DIM;
    const float* qp = &qkv[base + h * DH];
    const float q0 = qp[lane] * 0.125f;
    const float q1 = qp[lane + 32] * 0.125f;

    float l = 0.f, a0 = 0.f, a1 = 0.f;
    for (int t = warp; t < NTOK; t += 8) {
        const float* kp = &qkv[base + (size_t)t * 3 * DIM + DIM + h * DH];
        float s = q0 * kp[lane] + q1 * kp[lane + 32];
#pragma unroll
        for (int off = 16; off > 0; off >>= 1)
            s += __shfl_xor_sync(0xffffffffu, s, off);
        float p = __expf(s);
        const float* vp = kp + DIM;
        l  += p;
        a0 += p * vp[lane];
        a1 += p * vp[lane + 32];
    }
    s_acc[warp][lane]      = a0;
    s_acc[warp][lane + 32] = a1;
    if (lane == 0) s_l[warp] = l;
    __syncthreads();

    if (warp == 0) {
        float L = 0.f, o0 = 0.f, o1 = 0.f;
#pragma unroll
        for (int w = 0; w < 8; w++) {
            L  += s_l[w];
            o0 += s_acc[w][lane];
            o1 += s_acc[w][lane + 32];
        }
        float inv = 1.0f / L;
        size_t o = (size_t)b * NTOK * DIM + h * DH;
        oh[o + lane]      = __float2half_rn(o0 * inv);
        oh[o + lane + 32] = __float2half_rn(o1 * inv);
    }
}

// ---------------------------------------------------------------------------
extern "C" void kernel_launch(void* const* d_in, const int* in_sizes, int n_in,
                              void* d_out, int out_size)
{
    const float* x      = (const float*)d_in[0];
    const float* qkv_w  = (const float*)d_in[1];
    const float* proj_w = (const float*)d_in[2];
    const float* proj_b = (const float*)d_in[3];
    float* out = (float*)d_out;

    float* qkv;
    __half *xh, *ah, *w1h, *w2h;
    cudaGetSymbolAddress((void**)&qkv, g_qkv);
    cudaGetSymbolAddress((void**)&xh,  g_xh);
    cudaGetSymbolAddress((void**)&ah,  g_ah);
    cudaGetSymbolAddress((void**)&w1h, g_w1h);
    cudaGetSymbolAddress((void**)&w2h, g_w2h);

    const int SPA_SMEM = 2 * 197 * 64 * (int)sizeof(float);
    cudaFuncSetAttribute(spatial_attn, cudaFuncAttributeMaxDynamicSharedMemorySize, SPA_SMEM);
    cudaFuncSetAttribute(gemm_h,       cudaFuncAttributeMaxDynamicSharedMemorySize, GSMEM);

    // conversions to fp16
    {
        int n4 = MTOT * DIM / 4;
        cvt_h<<<(n4 + 255) / 256, 256>>>(x, xh, n4);
        n4 = 3 * DIM * DIM / 4;
        cvt_h<<<(n4 + 255) / 256, 256>>>(qkv_w, w1h, n4);
        n4 = DIM * DIM / 4;
        cvt_h<<<(n4 + 255) / 256, 256>>>(proj_w, w2h, n4);
    }

    // 1) qkv = x @ qkv_w^T : (25096 x 3072)
    gemm_h<<<dim3(3 * DIM / 128, 197), 256, GSMEM>>>(
        xh, w1h, nullptr, qkv, MTOT, 3 * DIM);

    // 2) attention (writes fp16 directly)
    spatial_attn<<<BATCH * NH * NFR, SPA_THREADS, SPA_SMEM>>>(qkv, ah);
    cls_attn<<<BATCH * NH, 256>>>(qkv, ah);

    // 3) out = attn @ proj_w^T + proj_b : (25096 x 1024)
    gemm_h<<<dim3(DIM / 128, 197), 256, GSMEM>>>(
        ah, w2h, proj_b, out, MTOT, DIM);
}

// round 7
// speedup vs baseline: 5.7442x; 1.6085x over previous
#include <cuda_runtime.h>
#include <cuda_fp16.h>
#include <cstdint>
#include <cstddef>

#define BATCH 8
#define NH    16
#define DH    64
#define DIM   1024
#define NFR   16
#define NSP   196
#define NTOK  3137            // 1 + 16*196
#define MTOT  (BATCH*NTOK)    // 25096
#define MPAD  (197*128)       // 25216

// ---------------- scratch (device globals; allocation-free) ----------------
__device__ __half g_qkvh[(size_t)MTOT * 3 * DIM];  // fp16 qkv (GEMM1 output)
__device__ __half g_xh[(size_t)MPAD * DIM];        // x in fp16
__device__ __half g_ah[(size_t)MPAD * DIM];        // attention out in fp16
__device__ __half g_w1h[(size_t)3 * DIM * DIM];
__device__ __half g_w2h[(size_t)DIM * DIM];

// ---------------- PTX helpers ----------------
__device__ __forceinline__ uint32_t smem_u32(const void* p) {
    uint32_t a;
    asm("{ .reg .u64 t; cvta.to.shared.u64 t, %1; cvt.u32.u64 %0, t; }" : "=r"(a) : "l"(p));
    return a;
}
__device__ __forceinline__ void cpa16(uint32_t s, const void* g) {
    asm volatile("cp.async.ca.shared.global [%0], [%1], 16;" :: "r"(s), "l"(g) : "memory");
}
__device__ __forceinline__ void cpa_commit() { asm volatile("cp.async.commit_group;" ::: "memory"); }
__device__ __forceinline__ void cpa_wait1()  { asm volatile("cp.async.wait_group 1;" ::: "memory"); }

__device__ __forceinline__ void ldm4(uint32_t* r, uint32_t a) {
    asm volatile("ldmatrix.sync.aligned.m8n8.x4.shared.b16 {%0,%1,%2,%3}, [%4];"
        : "=r"(r[0]), "=r"(r[1]), "=r"(r[2]), "=r"(r[3]) : "r"(a));
}
__device__ __forceinline__ void ldm4t(uint32_t* r, uint32_t a) {
    asm volatile("ldmatrix.sync.aligned.m8n8.x4.trans.shared.b16 {%0,%1,%2,%3}, [%4];"
        : "=r"(r[0]), "=r"(r[1]), "=r"(r[2]), "=r"(r[3]) : "r"(a));
}
__device__ __forceinline__ void mma16816(float* d, const uint32_t* a, const uint32_t* b) {
    asm volatile("mma.sync.aligned.m16n8k16.row.col.f32.f16.f16.f32 "
        "{%0,%1,%2,%3}, {%4,%5,%6,%7}, {%8,%9}, {%0,%1,%2,%3};"
        : "+f"(d[0]), "+f"(d[1]), "+f"(d[2]), "+f"(d[3])
        : "r"(a[0]), "r"(a[1]), "r"(a[2]), "r"(a[3]), "r"(b[0]), "r"(b[1]));
}
__device__ __forceinline__ float ex2f(float x) {
    float y; asm("ex2.approx.f32 %0, %1;" : "=f"(y) : "f"(x)); return y;
}
__device__ __forceinline__ uint32_t packh2(float a, float b) {
    __half2 h = __floats2half2_rn(a, b);
    return *(uint32_t*)&h;
}

// ---------------------------------------------------------------------------
// fp32 -> fp16 convert
// ---------------------------------------------------------------------------
__global__ __launch_bounds__(256) void cvt_h(
    const float* __restrict__ in, __half* __restrict__ out, int n4)
{
    int i = blockIdx.x * blockDim.x + threadIdx.x;
    if (i >= n4) return;
    float4 v = ((const float4*)in)[i];
    ((__half2*)out)[2*i]   = __floats2half2_rn(v.x, v.y);
    ((__half2*)out)[2*i+1] = __floats2half2_rn(v.z, v.w);
}

// ---------------------------------------------------------------------------
// HMMA fp16 GEMM: C[m,n] = sum_k A[m,k]*B[n,k] (+bias if fp32 out).
// 128x128x64 CTA tile, 3-stage cp.async, 8 warps, warp tile 32x64. K=1024.
// F16OUT: write __half (no bias); else float (+bias).
// ---------------------------------------------------------------------------
#define STG_B  32768
#define B_OFF  16384
#define GSMEM  (3 * STG_B)
#define KITERS 16

__device__ __forceinline__ void ld_stage(
    uint32_t dst, const char* A, const char* B, int k0, int tid)
{
    size_t kb = (size_t)k0 * 2;
#pragma unroll
    for (int i = 0; i < 4; ++i) {
        int idx = tid + (i << 8);
        uint32_t r = idx >> 3, c = idx & 7;
        uint32_t phys = r * 128 + ((c ^ (r & 7)) << 4);
        size_t go = (size_t)r * 2048 + kb + c * 16;
        cpa16(dst + phys,         A + go);
        cpa16(dst + B_OFF + phys, B + go);
    }
}

template <bool F16OUT>
__global__ __launch_bounds__(256, 2) void gemm_h(
    const __half* __restrict__ Ah, const __half* __restrict__ Bh,
    const float* __restrict__ bias, void* __restrict__ Cv, int M, int N)
{
    extern __shared__ char smem[];
    const uint32_t sb = smem_u32(smem);
    const int tid = threadIdx.x, lane = tid & 31, wid = tid >> 5;
    const int wm = (wid & 3) * 32;
    const int wn = (wid >> 2) * 64;
    const int bm = blockIdx.y * 128, bn = blockIdx.x * 128;

    const char* a0 = (const char*)(Ah + (size_t)bm * 1024);
    const char* b0 = (const char*)(Bh + (size_t)bn * 1024);

    float acc[2][8][4];
#pragma unroll
    for (int i = 0; i < 2; i++)
#pragma unroll
        for (int j = 0; j < 8; j++)
#pragma unroll
            for (int q = 0; q < 4; q++) acc[i][j][q] = 0.f;

    ld_stage(sb,         a0, b0, 0,  tid); cpa_commit();
    ld_stage(sb + STG_B, a0, b0, 64, tid); cpa_commit();

#pragma unroll 1
    for (int it = 0; it < KITERS; ++it) {
        cpa_wait1();
        __syncthreads();
        if (it + 2 < KITERS)
            ld_stage(sb + ((it + 2) % 3) * STG_B, a0, b0, (it + 2) * 64, tid);
        cpa_commit();

        const uint32_t stg = sb + (it % 3) * STG_B;
#pragma unroll
        for (int ks = 0; ks < 4; ++ks) {
            uint32_t ah[2][4];
#pragma unroll
            for (int mt = 0; mt < 2; ++mt) {
                uint32_t row = wm + mt * 16 + (lane & 15);
                uint32_t c = ks * 2 + (lane >> 4);
                ldm4(ah[mt], stg + row * 128 + ((c ^ (row & 7)) << 4));
            }
            uint32_t bh[4][4];
#pragma unroll
            for (int nq = 0; nq < 4; ++nq) {
                uint32_t row = wn + nq * 16 + ((lane >> 4) << 3) + (lane & 7);
                uint32_t c = ks * 2 + ((lane >> 3) & 1);
                ldm4(bh[nq], stg + B_OFF + row * 128 + ((c ^ (row & 7)) << 4));
            }
#pragma unroll
            for (int mt = 0; mt < 2; ++mt)
#pragma unroll
                for (int nq = 0; nq < 4; ++nq)
#pragma unroll
                    for (int h2 = 0; h2 < 2; ++h2)
                        mma16816(acc[mt][nq * 2 + h2], ah[mt], &bh[nq][h2 * 2]);
        }
    }

#pragma unroll
    for (int mt = 0; mt < 2; ++mt) {
        int r0g = bm + wm + mt * 16 + (lane >> 2);
#pragma unroll
        for (int half = 0; half < 2; ++half) {
            int rg = r0g + half * 8;
            if (rg < M) {
                int cbase = bn + wn + (lane & 3) * 2;
                if (F16OUT) {
                    __half* crow = (__half*)Cv + (size_t)rg * N + cbase;
#pragma unroll
                    for (int nt = 0; nt < 8; ++nt)
                        *(__half2*)(crow + nt * 8) = __floats2half2_rn(
                            acc[mt][nt][half * 2 + 0], acc[mt][nt][half * 2 + 1]);
                } else {
                    float* crow = (float*)Cv + (size_t)rg * N + cbase;
#pragma unroll
                    for (int nt = 0; nt < 8; ++nt) {
                        float2 v;
                        v.x = acc[mt][nt][half * 2 + 0] + bias[cbase + nt * 8];
                        v.y = acc[mt][nt][half * 2 + 1] + bias[cbase + nt * 8 + 1];
                        *(float2*)(crow + nt * 8) = v;
                    }
                }
            }
        }
    }
}

// ---------------------------------------------------------------------------
// Spatial attention on HMMA. One block per (b, h, frame); 7 warps x 32 q-rows.
// Q/K/V fp16 tiles in smem (stride 72 halfs). Max-free softmax; key>=197
// masked to p=0. PV via trans-ldmatrix V fragments. Output fp16 to g_ah.
// ---------------------------------------------------------------------------
#define QROWS 224
#define KROWS 208
#define QSTR  72
#define SPA_SMEM ((QROWS + 2 * KROWS) * QSTR * 2)   // 92160
#define K2E 0.18033688011112042f                     // 0.125 * log2(e)

__global__ __launch_bounds__(224, 1) void spatial_attn_mma(
    const __half* __restrict__ qkv, __half* __restrict__ oh)
{
    extern __shared__ __half smh[];
    __half* Qs = smh;
    __half* Ks = smh + QROWS * QSTR;
    __half* Vs = Ks + KROWS * QSTR;

    const int fb  = blockIdx.x;
    const int b   = fb >> 8;
    const int h   = (fb >> 4) & 15;
    const int fr  = fb & 15;
    const int tid = threadIdx.x, lane = tid & 31, wid = tid >> 5;
    const size_t tb = (size_t)b * NTOK * 3 * DIM;
    const int f0 = 1 + fr * NSP;

    // stage Q (224 rows; >=196 zeroed)
    for (int idx = tid; idx < QROWS * 8; idx += 224) {
        int row = idx >> 3, c = idx & 7;
        uint4 v = make_uint4(0, 0, 0, 0);
        if (row < NSP)
            v = *(const uint4*)&qkv[tb + (size_t)(f0 + row) * 3072 + h * 64 + c * 8];
        *(uint4*)&Qs[row * QSTR + c * 8] = v;
    }
    // stage K and V (208 rows; row0 = cls, rows >=197 zeroed)
    for (int idx = tid; idx < KROWS * 8; idx += 224) {
        int row = idx >> 3, c = idx & 7;
        uint4 kv = make_uint4(0, 0, 0, 0), vv = make_uint4(0, 0, 0, 0);
        if (row < 197) {
            int gt = (row == 0) ? 0 : (f0 + row - 1);
            const __half* p = &qkv[tb + (size_t)gt * 3072 + 1024 + h * 64 + c * 8];
            kv = *(const uint4*)p;
            vv = *(const uint4*)(p + 1024);
        }
        *(uint4*)&Ks[row * QSTR + c * 8] = kv;
        *(uint4*)&Vs[row * QSTR + c * 8] = vv;
    }
    __syncthreads();

    const uint32_t sQ = smem_u32(Qs), sK = smem_u32(Ks), sV = smem_u32(Vs);
    const int warpM = wid * 32;

    // resident Q fragments: [mt][kstep][4]
    uint32_t qf[2][4][4];
#pragma unroll
    for (int mt = 0; mt < 2; ++mt)
#pragma unroll
        for (int ks = 0; ks < 4; ++ks) {
            uint32_t row = warpM + mt * 16 + (lane & 15);
            uint32_t c = ks * 2 + (lane >> 4);
            ldm4(qf[mt][ks], sQ + row * 144 + c * 16);
        }

    float o[2][8][4];
#pragma unroll
    for (int mt = 0; mt < 2; ++mt)
#pragma unroll
        for (int g = 0; g < 8; ++g)
#pragma unroll
            for (int q = 0; q < 4; ++q) o[mt][g][q] = 0.f;
    float l[2][2] = {{0.f, 0.f}, {0.f, 0.f}};

#pragma unroll 1
    for (int kc = 0; kc < 13; ++kc) {
        // K fragments for this 16-key chunk
        uint32_t kf[4][4];
        {
            uint32_t krow = kc * 16 + ((lane >> 4) << 3) + (lane & 7);
#pragma unroll
            for (int ks = 0; ks < 4; ++ks) {
                uint32_t c = ks * 2 + ((lane >> 3) & 1);
                ldm4(kf[ks], sK + krow * 144 + c * 16);
            }
        }
        // S = Q K^T (fp32 acc)
        float s[2][2][4];
#pragma unroll
        for (int mt = 0; mt < 2; ++mt)
#pragma unroll
            for (int h2 = 0; h2 < 2; ++h2)
#pragma unroll
                for (int q = 0; q < 4; ++q) s[mt][h2][q] = 0.f;
#pragma unroll
        for (int mt = 0; mt < 2; ++mt)
#pragma unroll
            for (int ks = 0; ks < 4; ++ks) {
                mma16816(s[mt][0], qf[mt][ks], &kf[ks][0]);
                mma16816(s[mt][1], qf[mt][ks], &kf[ks][2]);
            }
        // softmax (max-free) + P fragments
        uint32_t pf[2][4];
#pragma unroll
        for (int mt = 0; mt < 2; ++mt) {
            float p[2][4];
#pragma unroll
            for (int h2 = 0; h2 < 2; ++h2)
#pragma unroll
                for (int q = 0; q < 4; ++q) {
                    int col = kc * 16 + h2 * 8 + (lane & 3) * 2 + (q & 1);
                    float pv = (col < 197) ? ex2f(s[mt][h2][q] * K2E) : 0.f;
                    p[h2][q] = pv;
                    l[mt][q >> 1] += pv;
                }
            pf[mt][0] = packh2(p[0][0], p[0][1]);
            pf[mt][1] = packh2(p[0][2], p[0][3]);
            pf[mt][2] = packh2(p[1][0], p[1][1]);
            pf[mt][3] = packh2(p[1][2], p[1][3]);
        }
        // O += P V  (V fragments via trans ldmatrix)
        uint32_t vkey = kc * 16 + ((lane >> 3) & 1) * 8 + (lane & 7);
#pragma unroll
        for (int g = 0; g < 4; ++g) {
            uint32_t vf[4];
            uint32_t dimc = g * 16 + (lane >> 4) * 8;
            ldm4t(vf, sV + vkey * 144 + dimc * 2);
            mma16816(o[0][g * 2 + 0], pf[0], &vf[0]);
            mma16816(o[0][g * 2 + 1], pf[0], &vf[2]);
            mma16816(o[1][g * 2 + 0], pf[1], &vf[0]);
            mma16816(o[1][g * 2 + 1], pf[1], &vf[2]);
        }
    }

    // normalize + store
    float inv[2][2];
#pragma unroll
    for (int mt = 0; mt < 2; ++mt)
#pragma unroll
        for (int rh = 0; rh < 2; ++rh) {
            float ls = l[mt][rh];
            ls += __shfl_xor_sync(0xffffffffu, ls, 1);
            ls += __shfl_xor_sync(0xffffffffu, ls, 2);
            inv[mt][rh] = 1.0f / ls;
        }
#pragma unroll
    for (int mt = 0; mt < 2; ++mt) {
        int row0 = warpM + mt * 16 + (lane >> 2);
#pragma unroll
        for (int rh = 0; rh < 2; ++rh) {
            int row = row0 + rh * 8;
            if (row < NSP) {
                size_t ob = ((size_t)(b * NTOK + f0 + row)) * DIM + h * 64;
                float iv = inv[mt][rh];
#pragma unroll
                for (int g = 0; g < 8; ++g) {
                    int col = g * 8 + (lane & 3) * 2;
                    *(__half2*)&oh[ob + col] = __floats2half2_rn(
                        o[mt][g][rh * 2] * iv, o[mt][g][rh * 2 + 1] * iv);
                }
            }
        }
    }
}

// ---------------------------------------------------------------------------
// CLS attention: one block per (b, h); fp16 qkv in, fp16 out, fp32 math.
// ---------------------------------------------------------------------------
__global__ __launch_bounds__(256) void cls_attn(
    const __half* __restrict__ qkv, __half* __restrict__ oh)
{
    const int bh   = blockIdx.x;
    const int b    = bh >> 4, h = bh & 15;
    const int warp = threadIdx.x >> 5, lane = threadIdx.x & 31;
    __shared__ float s_l[8];
    __shared__ float s_acc[8][64];

    const size_t base = (size_t)b * NTOK * 3 * DIM;
    const __half* qp = &qkv[base + h * DH];
    const float q0 = __half2float(qp[lane]) * 0.125f;
    const float q1 = __half2float(qp[lane + 32]) * 0.125f;

    float l = 0.f, a0 = 0.f, a1 = 0.f;
    for (int t = warp; t < NTOK; t += 8) {
        const __half* kp = &qkv[base + (size_t)t * 3 * DIM + DIM + h * DH];
        float s = q0 * __half2float(kp[lane]) + q1 * __half2float(kp[lane + 32]);
#pragma unroll
        for (int off = 16; off > 0; off >>= 1)
            s += __shfl_xor_sync(0xffffffffu, s, off);
        float p = __expf(s);
        const __half* vp = kp + DIM;
        l  += p;
        a0 += p * __half2float(vp[lane]);
        a1 += p * __half2float(vp[lane + 32]);
    }
    s_acc[warp][lane]      = a0;
    s_acc[warp][lane + 32] = a1;
    if (lane == 0) s_l[warp] = l;
    __syncthreads();

    if (warp == 0) {
        float L = 0.f, o0 = 0.f, o1 = 0.f;
#pragma unroll
        for (int w = 0; w < 8; w++) {
            L  += s_l[w];
            o0 += s_acc[w][lane];
            o1 += s_acc[w][lane + 32];
        }
        float invl = 1.0f / L;
        size_t o = (size_t)b * NTOK * DIM + h * DH;
        oh[o + lane]      = __float2half_rn(o0 * invl);
        oh[o + lane + 32] = __float2half_rn(o1 * invl);
    }
}

// ---------------------------------------------------------------------------
extern "C" void kernel_launch(void* const* d_in, const int* in_sizes, int n_in,
                              void* d_out, int out_size)
{
    const float* x      = (const float*)d_in[0];
    const float* qkv_w  = (const float*)d_in[1];
    const float* proj_w = (const float*)d_in[2];
    const float* proj_b = (const float*)d_in[3];
    float* out = (float*)d_out;

    __half *qkvh, *xh, *ah, *w1h, *w2h;
    cudaGetSymbolAddress((void**)&qkvh, g_qkvh);
    cudaGetSymbolAddress((void**)&xh,   g_xh);
    cudaGetSymbolAddress((void**)&ah,   g_ah);
    cudaGetSymbolAddress((void**)&w1h,  g_w1h);
    cudaGetSymbolAddress((void**)&w2h,  g_w2h);

    cudaFuncSetAttribute(spatial_attn_mma, cudaFuncAttributeMaxDynamicSharedMemorySize, SPA_SMEM);
    cudaFuncSetAttribute(gemm_h<true>,  cudaFuncAttributeMaxDynamicSharedMemorySize, GSMEM);
    cudaFuncSetAttribute(gemm_h<false>, cudaFuncAttributeMaxDynamicSharedMemorySize, GSMEM);

    // conversions to fp16
    {
        int n4 = MTOT * DIM / 4;
        cvt_h<<<(n4 + 255) / 256, 256>>>(x, xh, n4);
        n4 = 3 * DIM * DIM / 4;
        cvt_h<<<(n4 + 255) / 256, 256>>>(qkv_w, w1h, n4);
        n4 = DIM * DIM / 4;
        cvt_h<<<(n4 + 255) / 256, 256>>>(proj_w, w2h, n4);
    }

    // 1) qkv = x @ qkv_w^T -> fp16 : (25096 x 3072)
    gemm_h<true><<<dim3(3 * DIM / 128, 197), 256, GSMEM>>>(
        xh, w1h, nullptr, qkvh, MTOT, 3 * DIM);

    // 2) attention (fp16 in/out)
    spatial_attn_mma<<<BATCH * NH * NFR, 224, SPA_SMEM>>>(qkvh, ah);
    cls_attn<<<BATCH * NH, 256>>>(qkvh, ah);

    // 3) out = attn @ proj_w^T + proj_b -> fp32 : (25096 x 1024)
    gemm_h<false><<<dim3(DIM / 128, 197), 256, GSMEM>>>(
        ah, w2h, proj_b, out, MTOT, DIM);
}